// round 12
// baseline (speedup 1.0000x reference)
#include <cuda_runtime.h>

// GaussianBlur2D: circular Gaussian blur, separable, FUSED single kernel.
// x: [8,1,2048,2048] fp32, sigma_: scalar fp32. sigma ~= 2, radius 8
// (truncated+renormalized; end-to-end rel_err ~5.5e-5 << 1e-3).
//
// R11: static per-thread work assignment (no dynamic task loops), V-stage
// as col-pair x 16-row tasks (1 per thread, 33% fewer LDS + less halo
// re-read), and interior-CTA fast path without circular-wrap masks.

#define HDIM   2048
#define WDIM   2048
#define RAD    8
#define TILE   128                    // output tile (both dims)
#define SROWS  (TILE + 2 * RAD)       // 144 smem rows (H results incl halo)
#define HWIN   (8 + 2 * RAD)          // 24-elem H window feeds 8 outputs
#define VWIN   (16 + 2 * RAD)         // 32-row V window feeds 16 outputs
#define SMEM_BYTES (SROWS * TILE * 4) // 72 KB

typedef unsigned long long u64;

__device__ float g_wn[RAD + 1];       // normalized 1D weights

// ---- packed f32x2 helpers (sm_100+) ---------------------------------------
__device__ __forceinline__ u64 pack2(float lo, float hi) {
    u64 r; asm("mov.b64 %0, {%1, %2};" : "=l"(r) : "f"(lo), "f"(hi)); return r;
}
__device__ __forceinline__ void unpack2(u64 v, float& lo, float& hi) {
    asm("mov.b64 {%0, %1}, %2;" : "=f"(lo), "=f"(hi) : "l"(v));
}
__device__ __forceinline__ u64 fma2(u64 a, u64 b, u64 c) {
    u64 r; asm("fma.rn.f32x2 %0, %1, %2, %3;" : "=l"(r) : "l"(a), "l"(b), "l"(c));
    return r;
}

// ---------------------------------------------------------------------------
// Normalized 1D Gaussian weights from device-side sigma (truncated-sum
// normalization keeps the kernel sum exactly 1).
// ---------------------------------------------------------------------------
__global__ void gb_weights_kernel(const float* __restrict__ sigma_) {
    if (threadIdx.x == 0) {
        float s = fmaxf(sigma_[0], 0.0f) + 1e-6f;
        float inv2s2 = 1.0f / (2.0f * s * s);
        float w[RAD + 1];
        float sum = 0.0f;
        #pragma unroll
        for (int d = 0; d <= RAD; d++) {
            w[d] = expf(-(float)(d * d) * inv2s2);
            sum += (d == 0) ? w[d] : 2.0f * w[d];
        }
        float inv = 1.0f / sum;
        #pragma unroll
        for (int d = 0; d <= RAD; d++) g_wn[d] = w[d] * inv;
    }
}

// ---------------------------------------------------------------------------
// One H task: 2 rows x 8 cols, circular window along W from GLOBAL.
// Rows packed per-element into f32x2 (one weight-multiply serves both rows).
// W=false: interior CTA, no wrap masks -> plain strength-reduced addressing.
// ---------------------------------------------------------------------------
template <bool W>
__device__ __forceinline__ void h_task(
    const float* __restrict__ src, float* __restrict__ sh,
    const u64* __restrict__ wn2, int x0, int y0, int t)
{
    const int pr = t >> 4;                    // row pair 0..71
    const int cg = t & 15;                    // col group 0..15
    const int rA = 2 * pr;
    const int rB = rA + 1;
    int gA = y0 - RAD + rA;
    int gB = gA + 1;
    if (W) { gA &= (HDIM - 1); gB &= (HDIM - 1); }
    const float* __restrict__ rowA = src + (size_t)gA * WDIM;
    const float* __restrict__ rowB = src + (size_t)gB * WDIM;
    const int c0 = cg * 8;
    const int base = x0 + c0 - RAD;           // 4-aligned (RAD%4==0)

    u64 acc[8];
    #pragma unroll
    for (int k = 0; k < 8; k++) acc[k] = 0ull;

    #pragma unroll
    for (int g = 0; g < HWIN / 4; g++) {
        int idx = base + 4 * g;
        if (W) idx &= (WDIM - 1);             // groups never straddle the wrap
        float4 a = *reinterpret_cast<const float4*>(rowA + idx);
        float4 b = *reinterpret_cast<const float4*>(rowB + idx);
        const float ae[4] = {a.x, a.y, a.z, a.w};
        const float be[4] = {b.x, b.y, b.z, b.w};
        #pragma unroll
        for (int e = 0; e < 4; e++) {
            const int j = 4 * g + e;          // window pos 0..23
            u64 v = pack2(ae[e], be[e]);
            #pragma unroll
            for (int k = 0; k < 8; k++) {     // output k uses win[k..k+2R]
                const int d = j - RAD - k;    // compile-time
                if (d < -RAD || d > RAD) continue;
                const int ad = d < 0 ? -d : d;
                acc[k] = fma2(wn2[ad], v, acc[k]);
            }
        }
    }

    float la[8], lb[8];
    #pragma unroll
    for (int k = 0; k < 8; k++) unpack2(acc[k], la[k], lb[k]);
    float4* sA = reinterpret_cast<float4*>(sh + rA * TILE + c0);
    float4* sB = reinterpret_cast<float4*>(sh + rB * TILE + c0);
    sA[0] = make_float4(la[0], la[1], la[2], la[3]);
    sA[1] = make_float4(la[4], la[5], la[6], la[7]);
    sB[0] = make_float4(lb[0], lb[1], lb[2], lb[3]);
    sB[1] = make_float4(lb[4], lb[5], lb[6], lb[7]);
}

// ---------------------------------------------------------------------------
// One V task: 1 col-pair x 16 output rows. 32 LDS.64 down the smem tile
// (same-row warp access => conflict-free), 272 packed FMAs, coalesced
// STG.64 (a warp stores 256B contiguous per row). No wrap ever needed.
// ---------------------------------------------------------------------------
__device__ __forceinline__ void v_task(
    const float* __restrict__ sh, float* __restrict__ dst,
    const u64* __restrict__ wn2, int x0, int y0, int tid)
{
    const int cp    = tid & 63;               // col pair 0..63
    const int ygrp  = tid >> 6;               // 0..7
    const int c     = 2 * cp;
    const int ybase = 16 * ygrp;

    u64 acc[16];
    #pragma unroll
    for (int k = 0; k < 16; k++) acc[k] = 0ull;

    #pragma unroll
    for (int i = 0; i < VWIN; i++) {          // smem rows ybase .. ybase+31
        u64 v = *reinterpret_cast<const u64*>(sh + (ybase + i) * TILE + c);
        #pragma unroll
        for (int k = 0; k < 16; k++) {
            const int d = i - RAD - k;        // compile-time
            if (d < -RAD || d > RAD) continue;
            const int ad = d < 0 ? -d : d;
            acc[k] = fma2(wn2[ad], v, acc[k]);
        }
    }

    #pragma unroll
    for (int k = 0; k < 16; k++)
        *reinterpret_cast<u64*>(dst + (size_t)(y0 + ybase + k) * WDIM
                                    + x0 + c) = acc[k];
}

// ---------------------------------------------------------------------------
template <bool W>
__device__ __forceinline__ void gb_body(
    const float* __restrict__ src, float* __restrict__ dst,
    float* __restrict__ sh, int x0, int y0, int tid)
{
    u64 wn2[RAD + 1];
    #pragma unroll
    for (int d = 0; d <= RAD; d++) { float w = g_wn[d]; wn2[d] = pack2(w, w); }

    // H: 1152 tasks (72 row-pairs x 16 col-groups), statically assigned.
    h_task<W>(src, sh, wn2, x0, y0, tid);
    h_task<W>(src, sh, wn2, x0, y0, tid + 512);
    if (tid < 128) h_task<W>(src, sh, wn2, x0, y0, tid + 1024);

    __syncthreads();

    // V: 512 tasks, exactly one per thread.
    v_task(sh, dst, wn2, x0, y0, tid);
}

// ---------------------------------------------------------------------------
// Fused blur kernel. Grid (16,16,8), 512 threads, 72 KB dynamic smem.
// Interior CTAs (14x14 of 16x16 per image) take the mask-free fast path.
// ---------------------------------------------------------------------------
__global__ __launch_bounds__(512, 2) void gb_fused_kernel(
    const float* __restrict__ x, float* __restrict__ out)
{
    extern __shared__ float sh[];             // [SROWS][TILE]

    const int x0 = blockIdx.x * TILE;
    const int y0 = blockIdx.y * TILE;
    const float* __restrict__ src = x   + (size_t)blockIdx.z * HDIM * WDIM;
    float*       __restrict__ dst = out + (size_t)blockIdx.z * HDIM * WDIM;
    const int tid = threadIdx.x;

    const bool wrap = (blockIdx.x == 0) | (blockIdx.x == (WDIM / TILE - 1)) |
                      (blockIdx.y == 0) | (blockIdx.y == (HDIM / TILE - 1));
    if (!wrap) gb_body<false>(src, dst, sh, x0, y0, tid);
    else       gb_body<true >(src, dst, sh, x0, y0, tid);
}

// ---------------------------------------------------------------------------
extern "C" void kernel_launch(void* const* d_in, const int* in_sizes, int n_in,
                              void* d_out, int out_size)
{
    const float* x      = (const float*)d_in[0];
    const float* sigma_ = (const float*)d_in[1];
    float* out          = (float*)d_out;

    // idempotent; no allocation; capture-safe (host-side attribute set)
    cudaFuncSetAttribute(gb_fused_kernel,
                         cudaFuncAttributeMaxDynamicSharedMemorySize,
                         SMEM_BYTES);

    gb_weights_kernel<<<1, 32>>>(sigma_);

    dim3 grid(WDIM / TILE, HDIM / TILE, 8);   // 16 x 16 x 8 = 2048 CTAs
    gb_fused_kernel<<<grid, 512, SMEM_BYTES>>>(x, out);
}

// round 13
// speedup vs baseline: 1.0325x; 1.0325x over previous
#include <cuda_runtime.h>

// GaussianBlur2D: circular Gaussian blur, separable, FUSED single kernel.
// x: [8,1,2048,2048] fp32, sigma_: scalar fp32. sigma ~= 2, radius 8
// (truncated+renormalized; end-to-end rel_err ~5.5e-5 << 1e-3).
//
// R13: (1) weights computed inline per-CTA (removes the dependent 4.8us
// weights launch), (2) CTA split into two independent 64-col pipelines with
// named barriers so H (LDG+fma) and V (LDS+fma) phases overlap instead of
// convoying through one block-wide barrier, (3) V as 8-row tasks (16 acc
// regs, no spills).

#define HDIM   2048
#define WDIM   2048
#define RAD    8
#define TILE   128                    // output tile (both dims)
#define HALF   64                     // per-pipeline x-width
#define SROWS  (TILE + 2 * RAD)       // 144 smem rows (H results incl halo)
#define HWIN   (8 + 2 * RAD)          // 24-elem H window feeds 8 outputs
#define VWIN   (8 + 2 * RAD)          // 24-row V window feeds 8 outputs
#define HBUF   (SROWS * HALF)         // floats per half-buffer
#define SMEM_BYTES (2 * HBUF * 4)     // 72 KB

typedef unsigned long long u64;

// ---- packed f32x2 helpers (sm_100+) ---------------------------------------
__device__ __forceinline__ u64 pack2(float lo, float hi) {
    u64 r; asm("mov.b64 %0, {%1, %2};" : "=l"(r) : "f"(lo), "f"(hi)); return r;
}
__device__ __forceinline__ void unpack2(u64 v, float& lo, float& hi) {
    asm("mov.b64 {%0, %1}, %2;" : "=f"(lo), "=f"(hi) : "l"(v));
}
__device__ __forceinline__ u64 fma2(u64 a, u64 b, u64 c) {
    u64 r; asm("fma.rn.f32x2 %0, %1, %2, %3;" : "=l"(r) : "l"(a), "l"(b), "l"(c));
    return r;
}

// ---------------------------------------------------------------------------
// One H task: 2 rows x 8 cols of one 64-col half, circular window along W
// from GLOBAL. Rows packed per-element into f32x2. W=false: no wrap masks.
// t in [0,576): cg = t&7 (col group), pr = t>>3 (row pair 0..71).
// ---------------------------------------------------------------------------
template <bool W>
__device__ __forceinline__ void h_task(
    const float* __restrict__ src, float* __restrict__ shh,
    const u64* __restrict__ wn2, int xbase, int y0, int t)
{
    const int cg = t & 7;
    const int pr = t >> 3;
    const int rA = 2 * pr;
    const int rB = rA + 1;
    int gA = y0 - RAD + rA;
    int gB = gA + 1;
    if (W) { gA &= (HDIM - 1); gB &= (HDIM - 1); }
    const float* __restrict__ rowA = src + (size_t)gA * WDIM;
    const float* __restrict__ rowB = src + (size_t)gB * WDIM;
    const int c0 = cg * 8;                    // local col within half
    const int base = xbase + c0 - RAD;        // 4-aligned (RAD%4==0)

    u64 acc[8];
    #pragma unroll
    for (int k = 0; k < 8; k++) acc[k] = 0ull;

    #pragma unroll
    for (int g = 0; g < HWIN / 4; g++) {
        int idx = base + 4 * g;
        if (W) idx &= (WDIM - 1);             // groups never straddle the wrap
        float4 a = *reinterpret_cast<const float4*>(rowA + idx);
        float4 b = *reinterpret_cast<const float4*>(rowB + idx);
        const float ae[4] = {a.x, a.y, a.z, a.w};
        const float be[4] = {b.x, b.y, b.z, b.w};
        #pragma unroll
        for (int e = 0; e < 4; e++) {
            const int j = 4 * g + e;          // window pos 0..23
            u64 v = pack2(ae[e], be[e]);
            #pragma unroll
            for (int k = 0; k < 8; k++) {     // output k uses win[k..k+2R]
                const int d = j - RAD - k;    // compile-time
                if (d < -RAD || d > RAD) continue;
                const int ad = d < 0 ? -d : d;
                acc[k] = fma2(wn2[ad], v, acc[k]);
            }
        }
    }

    float la[8], lb[8];
    #pragma unroll
    for (int k = 0; k < 8; k++) unpack2(acc[k], la[k], lb[k]);
    float4* sA = reinterpret_cast<float4*>(shh + rA * HALF + c0);
    float4* sB = reinterpret_cast<float4*>(shh + rB * HALF + c0);
    sA[0] = make_float4(la[0], la[1], la[2], la[3]);
    sA[1] = make_float4(la[4], la[5], la[6], la[7]);
    sB[0] = make_float4(lb[0], lb[1], lb[2], lb[3]);
    sB[1] = make_float4(lb[4], lb[5], lb[6], lb[7]);
}

// ---------------------------------------------------------------------------
// One V task: 1 col-pair x 8 output rows of one half. 24 LDS.64 down the
// smem half (warp = 32 col-pairs = full 256B row, conflict-free), 136 packed
// FMAs, coalesced STG.64. t in [0,512): cp = t&31, ygrp = t>>5 (0..15).
// ---------------------------------------------------------------------------
__device__ __forceinline__ void v_task(
    const float* __restrict__ shh, float* __restrict__ dst,
    const u64* __restrict__ wn2, int xbase, int y0, int t)
{
    const int cp    = t & 31;
    const int ygrp  = t >> 5;
    const int c     = 2 * cp;
    const int ybase = 8 * ygrp;

    u64 acc[8];
    #pragma unroll
    for (int k = 0; k < 8; k++) acc[k] = 0ull;

    #pragma unroll
    for (int i = 0; i < VWIN; i++) {          // smem rows ybase .. ybase+23
        u64 v = *reinterpret_cast<const u64*>(shh + (ybase + i) * HALF + c);
        #pragma unroll
        for (int k = 0; k < 8; k++) {
            const int d = i - RAD - k;        // compile-time
            if (d < -RAD || d > RAD) continue;
            const int ad = d < 0 ? -d : d;
            acc[k] = fma2(wn2[ad], v, acc[k]);
        }
    }

    #pragma unroll
    for (int k = 0; k < 8; k++)
        *reinterpret_cast<u64*>(dst + (size_t)(y0 + ybase + k) * WDIM
                                    + xbase + c) = acc[k];
}

// ---------------------------------------------------------------------------
template <bool W>
__device__ __forceinline__ void gb_body(
    const float* __restrict__ src, float* __restrict__ dst,
    float* __restrict__ shh, const u64* __restrict__ wn2,
    int xbase, int y0, int ltid, int barid)
{
    // H: 576 tasks (72 row-pairs x 8 col-groups) over 256 threads.
    h_task<W>(src, shh, wn2, xbase, y0, ltid);
    h_task<W>(src, shh, wn2, xbase, y0, ltid + 256);
    if (ltid < 64) h_task<W>(src, shh, wn2, xbase, y0, ltid + 512);

    // Named barrier over this half's 256 threads only (drains STS).
    asm volatile("bar.sync %0, 256;" :: "r"(barid) : "memory");

    // V: 512 tasks over 256 threads.
    v_task(shh, dst, wn2, xbase, y0, ltid);
    v_task(shh, dst, wn2, xbase, y0, ltid + 256);
}

// ---------------------------------------------------------------------------
// Fused blur kernel. Grid (16,16,8), 512 threads, 72 KB dynamic smem.
// Threads [0,256) process the left 64-col half, [256,512) the right half —
// two independent pipelines whose H (LDG+fma) and V (LDS+fma) phases
// overlap within the SM. Weights computed inline (uniform; ~9 expf).
// ---------------------------------------------------------------------------
__global__ __launch_bounds__(512, 2) void gb_fused_kernel(
    const float* __restrict__ x, const float* __restrict__ sigma_,
    float* __restrict__ out)
{
    extern __shared__ float sh[];             // [2][SROWS*HALF]

    const int tid  = threadIdx.x;
    const int half = tid >> 8;                // 0 or 1 (warp-uniform)
    const int ltid = tid & 255;

    const int x0 = blockIdx.x * TILE;
    const int y0 = blockIdx.y * TILE;
    const int xbase = x0 + half * HALF;
    const float* __restrict__ src = x   + (size_t)blockIdx.z * HDIM * WDIM;
    float*       __restrict__ dst = out + (size_t)blockIdx.z * HDIM * WDIM;
    float* __restrict__ shh = sh + half * HBUF;

    // ---- inline normalized 1D Gaussian weights (uniform across threads) ----
    u64 wn2[RAD + 1];
    {
        float s = fmaxf(sigma_[0], 0.0f) + 1e-6f;
        float inv2s2 = 1.0f / (2.0f * s * s);
        float w[RAD + 1];
        float sum = 0.0f;
        #pragma unroll
        for (int d = 0; d <= RAD; d++) {
            w[d] = expf(-(float)(d * d) * inv2s2);
            sum += (d == 0) ? w[d] : 2.0f * w[d];
        }
        float inv = 1.0f / sum;
        #pragma unroll
        for (int d = 0; d <= RAD; d++) {
            float wd = w[d] * inv;
            wn2[d] = pack2(wd, wd);
        }
    }

    const bool wrap = (blockIdx.x == 0) | (blockIdx.x == (WDIM / TILE - 1)) |
                      (blockIdx.y == 0) | (blockIdx.y == (HDIM / TILE - 1));
    if (!wrap) gb_body<false>(src, dst, shh, wn2, xbase, y0, ltid, 1 + half);
    else       gb_body<true >(src, dst, shh, wn2, xbase, y0, ltid, 1 + half);
}

// ---------------------------------------------------------------------------
extern "C" void kernel_launch(void* const* d_in, const int* in_sizes, int n_in,
                              void* d_out, int out_size)
{
    const float* x      = (const float*)d_in[0];
    const float* sigma_ = (const float*)d_in[1];
    float* out          = (float*)d_out;

    // idempotent; no allocation; capture-safe (host-side attribute set)
    cudaFuncSetAttribute(gb_fused_kernel,
                         cudaFuncAttributeMaxDynamicSharedMemorySize,
                         SMEM_BYTES);

    dim3 grid(WDIM / TILE, HDIM / TILE, 8);   // 16 x 16 x 8 = 2048 CTAs
    gb_fused_kernel<<<grid, 512, SMEM_BYTES>>>(x, sigma_, out);
}